// round 3
// baseline (speedup 1.0000x reference)
#include <cuda_runtime.h>
#include <cuda_fp16.h>

#define NN 100000
#define NE_CAP 1700000
#define NB_SCAN 98   /* ceil(100000/1024) */

// ---- scratch (device globals: allocation-free) ----
__device__ __align__(16) __half g_Z[NN * 64];   // fp16 intermediate (12.8 MB, L2-resident)
__device__ __align__(16) float  g_H[NN * 64];
__device__ float g_onorm[NN];
__device__ float g_inorm[NN];
__device__ int   g_cout[NN];
__device__ int   g_cin[NN];
__device__ int   g_ptr[NN + 1];
__device__ int   g_fill[NN];
__device__ int   g_csr[NE_CAP];
__device__ int   g_part[NB_SCAN];

// ---------------- graph preprocessing ----------------
__global__ void k_degree(const int* __restrict__ src, const int* __restrict__ dst,
                         int* cout, int* cin, int E) {
    int i = blockIdx.x * blockDim.x + threadIdx.x;
    if (i < E) {
        atomicAdd(&cout[src[i]], 1);
        atomicAdd(&cin[dst[i]], 1);
    }
}

__global__ void k_norm(const int* __restrict__ cout, const int* __restrict__ cin,
                       float* onorm, float* inorm) {
    int i = blockIdx.x * blockDim.x + threadIdx.x;
    if (i < NN) {
        // +1 for the self loop; degree always >= 1 so no max() needed
        onorm[i] = rsqrtf((float)(cout[i] + 1));
        inorm[i] = rsqrtf((float)(cin[i] + 1));
    }
}

__global__ void k_scan_partial(const int* __restrict__ cin, int* part) {
    __shared__ int wsum[8];
    int b = blockIdx.x, t = threadIdx.x;
    int base = b * 1024 + t * 4;
    int s = 0;
#pragma unroll
    for (int j = 0; j < 4; j++) { int i = base + j; if (i < NN) s += cin[i]; }
    for (int o = 16; o > 0; o >>= 1) s += __shfl_down_sync(0xffffffffu, s, o);
    if ((t & 31) == 0) wsum[t >> 5] = s;
    __syncthreads();
    if (t == 0) {
        int tot = 0;
        for (int w = 0; w < 8; w++) tot += wsum[w];
        part[b] = tot;
    }
}

__global__ void k_scan_offsets(int* part, int* ptr) {
    int run = 0;
    for (int b = 0; b < NB_SCAN; b++) { int v = part[b]; part[b] = run; run += v; }
    ptr[NN] = run;
}

__global__ void k_scan_write(const int* __restrict__ cin, const int* __restrict__ part,
                             int* ptr, int* fill) {
    __shared__ int wexc[8];
    int b = blockIdx.x, t = threadIdx.x;
    int lane = t & 31, warp = t >> 5;
    int base = b * 1024 + t * 4;
    int v[4];
#pragma unroll
    for (int j = 0; j < 4; j++) { int i = base + j; v[j] = (i < NN) ? cin[i] : 0; }
    int s = v[0] + v[1] + v[2] + v[3];
    int inc = s;
    for (int o = 1; o < 32; o <<= 1) {
        int u = __shfl_up_sync(0xffffffffu, inc, o);
        if (lane >= o) inc += u;
    }
    if (lane == 31) wexc[warp] = inc;
    __syncthreads();
    if (warp == 0) {
        int w = (lane < 8) ? wexc[lane] : 0;
        int winc = w;
        for (int o = 1; o < 8; o <<= 1) {
            int u = __shfl_up_sync(0xffffffffu, winc, o);
            if (lane >= o) winc += u;
        }
        if (lane < 8) wexc[lane] = winc - w;  // exclusive warp offsets
    }
    __syncthreads();
    int pos = part[b] + wexc[warp] + (inc - s);
#pragma unroll
    for (int j = 0; j < 4; j++) {
        int i = base + j;
        if (i < NN) { ptr[i] = pos; fill[i] = pos; }
        pos += v[j];
    }
}

__global__ void k_fill(const int* __restrict__ src, const int* __restrict__ dst,
                       int* fill, int* csr, int E) {
    int i = blockIdx.x * blockDim.x + threadIdx.x;
    if (i < E) {
        int p = atomicAdd(&fill[dst[i]], 1);
        csr[p] = src[i];
    }
}

// ---------------- dense GEMM: Z = fp16( out_norm .* (A @ W) ), A is [NN,K] f32, W is [K,64] f32 ----------------
// Whole W lives in smem (one load + one sync). A streams from GMEM through a
// register double buffer; lanes sharing tr broadcast-load the same A addresses.
template <int K>
__global__ void __launch_bounds__(128, 2) k_gemm(const float* __restrict__ A,
                                                 const float* __restrict__ W,
                                                 const float* __restrict__ onorm,
                                                 __half* __restrict__ Z) {
    __shared__ float Bs[K * 64];
    const int tid = threadIdx.x;
    {
        const float4* wp = reinterpret_cast<const float4*>(W);
        float4* bs = reinterpret_cast<float4*>(Bs);
#pragma unroll
        for (int i = 0; i < (K * 16) / 128; i++)
            bs[tid + i * 128] = wp[tid + i * 128];
    }
    __syncthreads();

    const int tr = tid >> 3, tc = tid & 7;
    const int row0 = blockIdx.x * 128 + tr * 8;

    const float* ap[8];
#pragma unroll
    for (int i = 0; i < 8; i++) {
        int r = row0 + i;
        if (r > NN - 1) r = NN - 1;   // clamp: loads stay valid, stores guarded later
        ap[i] = A + (long)r * K;
    }

    float acc[8][8];
#pragma unroll
    for (int i = 0; i < 8; i++)
#pragma unroll
        for (int j = 0; j < 8; j++) acc[i][j] = 0.f;

    float4 buf0[8], buf1[8];
#pragma unroll
    for (int i = 0; i < 8; i++) buf0[i] = *reinterpret_cast<const float4*>(ap[i]);

#pragma unroll 2
    for (int k0 = 0; k0 < K; k0 += 8) {
        // prefetch second half of this 8-chunk
#pragma unroll
        for (int i = 0; i < 8; i++)
            buf1[i] = *reinterpret_cast<const float4*>(ap[i] + k0 + 4);
        // compute k0..k0+3 from buf0
#pragma unroll
        for (int kk = 0; kk < 4; kk++) {
            float4 w0 = *reinterpret_cast<const float4*>(&Bs[(k0 + kk) * 64 + tc * 8]);
            float4 w1 = *reinterpret_cast<const float4*>(&Bs[(k0 + kk) * 64 + tc * 8 + 4]);
            float wv[8] = {w0.x, w0.y, w0.z, w0.w, w1.x, w1.y, w1.z, w1.w};
#pragma unroll
            for (int i = 0; i < 8; i++) {
                float a = (kk == 0) ? buf0[i].x : (kk == 1) ? buf0[i].y
                        : (kk == 2) ? buf0[i].z : buf0[i].w;
#pragma unroll
                for (int j = 0; j < 8; j++) acc[i][j] += a * wv[j];
            }
        }
        // prefetch first half of next 8-chunk
        if (k0 + 8 < K) {
#pragma unroll
            for (int i = 0; i < 8; i++)
                buf0[i] = *reinterpret_cast<const float4*>(ap[i] + k0 + 8);
        }
        // compute k0+4..k0+7 from buf1
#pragma unroll
        for (int kk = 0; kk < 4; kk++) {
            float4 w0 = *reinterpret_cast<const float4*>(&Bs[(k0 + 4 + kk) * 64 + tc * 8]);
            float4 w1 = *reinterpret_cast<const float4*>(&Bs[(k0 + 4 + kk) * 64 + tc * 8 + 4]);
            float wv[8] = {w0.x, w0.y, w0.z, w0.w, w1.x, w1.y, w1.z, w1.w};
#pragma unroll
            for (int i = 0; i < 8; i++) {
                float a = (kk == 0) ? buf1[i].x : (kk == 1) ? buf1[i].y
                        : (kk == 2) ? buf1[i].z : buf1[i].w;
#pragma unroll
                for (int j = 0; j < 8; j++) acc[i][j] += a * wv[j];
            }
        }
    }

#pragma unroll
    for (int i = 0; i < 8; i++) {
        int r = row0 + i;
        if (r < NN) {
            float sc = onorm[r];
            __half2 oo[4];
#pragma unroll
            for (int j = 0; j < 4; j++)
                oo[j] = __floats2half2_rn(acc[i][2 * j] * sc, acc[i][2 * j + 1] * sc);
            // 8 halfs = 16 bytes, 16B-aligned (row byte offset r*128 + tc*16)
            *reinterpret_cast<uint4*>(Z + (long)r * 64 + tc * 8) =
                *reinterpret_cast<uint4*>(oo);
        }
    }
}

// ---------------- SpMM gather: Hout[v] = inorm[v]*(sum_{e:dst=v} Z[src_e] + Z[v]) + b ----------------
// Z rows are fp16 (128 B). Lane l owns features {2l, 2l+1} via one half2 load per edge.
// Inner loop batches 8 edges so 8 LDGs are in flight (MLP=8) before accumulation.
__global__ void __launch_bounds__(256) k_gather(const __half* __restrict__ Z,
                                                const int* __restrict__ ptr,
                                                const int* __restrict__ csr,
                                                const float* __restrict__ inorm,
                                                const float* __restrict__ bias,
                                                float* __restrict__ Hout) {
    int v = (blockIdx.x * blockDim.x + threadIdx.x) >> 5;
    int lane = threadIdx.x & 31;
    if (v >= NN) return;
    int beg = ptr[v], end = ptr[v + 1];

    // self loop contribution
    float2 f0 = __half22float2(*reinterpret_cast<const __half2*>(Z + (long)v * 64 + lane * 2));
    float acc0 = f0.x, acc1 = f0.y;

    for (int e0 = beg; e0 < end; e0 += 32) {
        int navail = end - e0;
        if (navail > 32) navail = 32;
        int s = (lane < navail) ? csr[e0 + lane] : 0;
        for (int j = 0; j < navail; j += 8) {
            int m = navail - j;
            if (m > 8) m = 8;
            float2 f[8];
#pragma unroll
            for (int t = 0; t < 8; t++) {
                if (t < m) {  // warp-uniform predicate
                    int sj = __shfl_sync(0xffffffffu, s, j + t);
                    f[t] = __half22float2(
                        *reinterpret_cast<const __half2*>(Z + (long)sj * 64 + lane * 2));
                }
            }
#pragma unroll
            for (int t = 0; t < 8; t++) {
                if (t < m) { acc0 += f[t].x; acc1 += f[t].y; }
            }
        }
    }
    float ni = inorm[v];
    float2 bb = *reinterpret_cast<const float2*>(bias + lane * 2);
    float2 out = make_float2(ni * acc0 + bb.x, ni * acc1 + bb.y);
    *reinterpret_cast<float2*>(Hout + (long)v * 64 + lane * 2) = out;
}

__global__ void k_ids(const int* __restrict__ ids, float* out, int n) {
    int i = blockIdx.x * blockDim.x + threadIdx.x;
    if (i < n) out[NN * 64 + i] = (float)ids[i];
}

// ---------------- launch ----------------
extern "C" void kernel_launch(void* const* d_in, const int* in_sizes, int n_in,
                              void* d_out, int out_size) {
    const float* h   = (const float*)d_in[0];
    const int*   src = (const int*)d_in[1];
    const int*   dst = (const int*)d_in[2];
    const int*   ids = (const int*)d_in[3];
    const float* W0  = (const float*)d_in[4];
    const float* b0  = (const float*)d_in[5];
    const float* W1  = (const float*)d_in[6];
    const float* b1  = (const float*)d_in[7];
    const float* W2  = (const float*)d_in[8];
    const float* b2  = (const float*)d_in[9];
    float* out = (float*)d_out;
    int E = in_sizes[1];

    __half* pZ;
    float *pH, *pon, *pin;
    int *pcout, *pcin, *pptr, *pfill, *pcsr, *ppart;
    cudaGetSymbolAddress((void**)&pZ, g_Z);
    cudaGetSymbolAddress((void**)&pH, g_H);
    cudaGetSymbolAddress((void**)&pon, g_onorm);
    cudaGetSymbolAddress((void**)&pin, g_inorm);
    cudaGetSymbolAddress((void**)&pcout, g_cout);
    cudaGetSymbolAddress((void**)&pcin, g_cin);
    cudaGetSymbolAddress((void**)&pptr, g_ptr);
    cudaGetSymbolAddress((void**)&pfill, g_fill);
    cudaGetSymbolAddress((void**)&pcsr, g_csr);
    cudaGetSymbolAddress((void**)&ppart, g_part);

    cudaMemsetAsync(pcout, 0, NN * sizeof(int));
    cudaMemsetAsync(pcin, 0, NN * sizeof(int));
    k_degree<<<(E + 255) / 256, 256>>>(src, dst, pcout, pcin, E);
    k_norm<<<(NN + 255) / 256, 256>>>(pcout, pcin, pon, pin);
    k_scan_partial<<<NB_SCAN, 256>>>(pcin, ppart);
    k_scan_offsets<<<1, 1>>>(ppart, pptr);
    k_scan_write<<<NB_SCAN, 256>>>(pcin, ppart, pptr, pfill);
    k_fill<<<(E + 255) / 256, 256>>>(src, dst, pfill, pcsr, E);

    const int gblk = (NN + 127) / 128;
    const int wblk = (NN * 32 + 255) / 256;

    k_gemm<128><<<gblk, 128>>>(h, W0, pon, pZ);
    k_gather<<<wblk, 256>>>(pZ, pptr, pcsr, pin, b0, pH);
    k_gemm<64><<<gblk, 128>>>(pH, W1, pon, pZ);
    k_gather<<<wblk, 256>>>(pZ, pptr, pcsr, pin, b1, pH);
    k_gemm<64><<<gblk, 128>>>(pH, W2, pon, pZ);
    k_gather<<<wblk, 256>>>(pZ, pptr, pcsr, pin, b2, out);

    if (out_size > NN * 64) {
        int nid = out_size - NN * 64;
        if (nid > in_sizes[3]) nid = in_sizes[3];
        k_ids<<<(nid + 255) / 256, 256>>>(ids, out, nid);
    }
}

// round 4
// speedup vs baseline: 1.3656x; 1.3656x over previous
#include <cuda_runtime.h>
#include <cuda_fp16.h>

#define NN 100000
#define NE_CAP 1700000
#define NB_SCAN 98   /* ceil(100000/1024) */

// ---- scratch (device globals: allocation-free) ----
__device__ __align__(16) __half g_Z[NN * 64];   // fp16 intermediate (12.8 MB, L2-resident)
__device__ __align__(16) float  g_H[NN * 64];
__device__ float g_onorm[NN];
__device__ float g_inorm[NN];
__device__ int   g_cout[NN];
__device__ int   g_cin[NN];
__device__ int   g_ptr[NN + 1];
__device__ int   g_fill[NN];
__device__ int   g_csr[NE_CAP];
__device__ int   g_part[NB_SCAN];

// ---------------- graph preprocessing ----------------
__global__ void k_degree(const int* __restrict__ src, const int* __restrict__ dst,
                         int* cout, int* cin, int E) {
    int i = blockIdx.x * blockDim.x + threadIdx.x;
    if (i < E) {
        atomicAdd(&cout[src[i]], 1);
        atomicAdd(&cin[dst[i]], 1);
    }
}

__global__ void k_norm(const int* __restrict__ cout, const int* __restrict__ cin,
                       float* onorm, float* inorm) {
    int i = blockIdx.x * blockDim.x + threadIdx.x;
    if (i < NN) {
        // +1 for the self loop; degree always >= 1 so no max() needed
        onorm[i] = rsqrtf((float)(cout[i] + 1));
        inorm[i] = rsqrtf((float)(cin[i] + 1));
    }
}

__global__ void k_scan_partial(const int* __restrict__ cin, int* part) {
    __shared__ int wsum[8];
    int b = blockIdx.x, t = threadIdx.x;
    int base = b * 1024 + t * 4;
    int s = 0;
#pragma unroll
    for (int j = 0; j < 4; j++) { int i = base + j; if (i < NN) s += cin[i]; }
    for (int o = 16; o > 0; o >>= 1) s += __shfl_down_sync(0xffffffffu, s, o);
    if ((t & 31) == 0) wsum[t >> 5] = s;
    __syncthreads();
    if (t == 0) {
        int tot = 0;
        for (int w = 0; w < 8; w++) tot += wsum[w];
        part[b] = tot;
    }
}

__global__ void k_scan_offsets(int* part, int* ptr) {
    int run = 0;
    for (int b = 0; b < NB_SCAN; b++) { int v = part[b]; part[b] = run; run += v; }
    ptr[NN] = run;
}

__global__ void k_scan_write(const int* __restrict__ cin, const int* __restrict__ part,
                             int* ptr, int* fill) {
    __shared__ int wexc[8];
    int b = blockIdx.x, t = threadIdx.x;
    int lane = t & 31, warp = t >> 5;
    int base = b * 1024 + t * 4;
    int v[4];
#pragma unroll
    for (int j = 0; j < 4; j++) { int i = base + j; v[j] = (i < NN) ? cin[i] : 0; }
    int s = v[0] + v[1] + v[2] + v[3];
    int inc = s;
    for (int o = 1; o < 32; o <<= 1) {
        int u = __shfl_up_sync(0xffffffffu, inc, o);
        if (lane >= o) inc += u;
    }
    if (lane == 31) wexc[warp] = inc;
    __syncthreads();
    if (warp == 0) {
        int w = (lane < 8) ? wexc[lane] : 0;
        int winc = w;
        for (int o = 1; o < 8; o <<= 1) {
            int u = __shfl_up_sync(0xffffffffu, winc, o);
            if (lane >= o) winc += u;
        }
        if (lane < 8) wexc[lane] = winc - w;  // exclusive warp offsets
    }
    __syncthreads();
    int pos = part[b] + wexc[warp] + (inc - s);
#pragma unroll
    for (int j = 0; j < 4; j++) {
        int i = base + j;
        if (i < NN) { ptr[i] = pos; fill[i] = pos; }
        pos += v[j];
    }
}

__global__ void k_fill(const int* __restrict__ src, const int* __restrict__ dst,
                       int* fill, int* csr, int E) {
    int i = blockIdx.x * blockDim.x + threadIdx.x;
    if (i < E) {
        int p = atomicAdd(&fill[dst[i]], 1);
        csr[p] = src[i];
    }
}

// ---------------- dense GEMM: Z = fp16( out_norm .* (A @ W) ), A is [NN,K] f32, W is [K,64] f32 ----------------
// Whole W lives in smem (one load + one sync). A streams from GMEM through a
// register double buffer; lanes sharing tr broadcast-load the same A addresses.
template <int K>
__global__ void __launch_bounds__(128, 2) k_gemm(const float* __restrict__ A,
                                                 const float* __restrict__ W,
                                                 const float* __restrict__ onorm,
                                                 __half* __restrict__ Z) {
    __shared__ float Bs[K * 64];
    const int tid = threadIdx.x;
    {
        const float4* wp = reinterpret_cast<const float4*>(W);
        float4* bs = reinterpret_cast<float4*>(Bs);
#pragma unroll
        for (int i = 0; i < (K * 16) / 128; i++)
            bs[tid + i * 128] = wp[tid + i * 128];
    }
    __syncthreads();

    const int tr = tid >> 3, tc = tid & 7;
    const int row0 = blockIdx.x * 128 + tr * 8;

    const float* ap[8];
#pragma unroll
    for (int i = 0; i < 8; i++) {
        int r = row0 + i;
        if (r > NN - 1) r = NN - 1;   // clamp: loads stay valid, stores guarded later
        ap[i] = A + (long)r * K;
    }

    float acc[8][8];
#pragma unroll
    for (int i = 0; i < 8; i++)
#pragma unroll
        for (int j = 0; j < 8; j++) acc[i][j] = 0.f;

    float4 buf0[8], buf1[8];
#pragma unroll
    for (int i = 0; i < 8; i++) buf0[i] = *reinterpret_cast<const float4*>(ap[i]);

#pragma unroll 2
    for (int k0 = 0; k0 < K; k0 += 8) {
        // prefetch second half of this 8-chunk
#pragma unroll
        for (int i = 0; i < 8; i++)
            buf1[i] = *reinterpret_cast<const float4*>(ap[i] + k0 + 4);
        // compute k0..k0+3 from buf0
#pragma unroll
        for (int kk = 0; kk < 4; kk++) {
            float4 w0 = *reinterpret_cast<const float4*>(&Bs[(k0 + kk) * 64 + tc * 8]);
            float4 w1 = *reinterpret_cast<const float4*>(&Bs[(k0 + kk) * 64 + tc * 8 + 4]);
            float wv[8] = {w0.x, w0.y, w0.z, w0.w, w1.x, w1.y, w1.z, w1.w};
#pragma unroll
            for (int i = 0; i < 8; i++) {
                float a = (kk == 0) ? buf0[i].x : (kk == 1) ? buf0[i].y
                        : (kk == 2) ? buf0[i].z : buf0[i].w;
#pragma unroll
                for (int j = 0; j < 8; j++) acc[i][j] += a * wv[j];
            }
        }
        // prefetch first half of next 8-chunk
        if (k0 + 8 < K) {
#pragma unroll
            for (int i = 0; i < 8; i++)
                buf0[i] = *reinterpret_cast<const float4*>(ap[i] + k0 + 8);
        }
        // compute k0+4..k0+7 from buf1
#pragma unroll
        for (int kk = 0; kk < 4; kk++) {
            float4 w0 = *reinterpret_cast<const float4*>(&Bs[(k0 + 4 + kk) * 64 + tc * 8]);
            float4 w1 = *reinterpret_cast<const float4*>(&Bs[(k0 + 4 + kk) * 64 + tc * 8 + 4]);
            float wv[8] = {w0.x, w0.y, w0.z, w0.w, w1.x, w1.y, w1.z, w1.w};
#pragma unroll
            for (int i = 0; i < 8; i++) {
                float a = (kk == 0) ? buf1[i].x : (kk == 1) ? buf1[i].y
                        : (kk == 2) ? buf1[i].z : buf1[i].w;
#pragma unroll
                for (int j = 0; j < 8; j++) acc[i][j] += a * wv[j];
            }
        }
    }

#pragma unroll
    for (int i = 0; i < 8; i++) {
        int r = row0 + i;
        if (r < NN) {
            float sc = onorm[r];
            __half2 oo[4];
#pragma unroll
            for (int j = 0; j < 4; j++)
                oo[j] = __floats2half2_rn(acc[i][2 * j] * sc, acc[i][2 * j + 1] * sc);
            // 8 halfs = 16 bytes, 16B-aligned (row byte offset r*128 + tc*16)
            *reinterpret_cast<uint4*>(Z + (long)r * 64 + tc * 8) =
                *reinterpret_cast<uint4*>(oo);
        }
    }
}

// ---------------- SpMM gather: Hout[v] = inorm[v]*(sum_{e:dst=v} Z[src_e] + Z[v]) + b ----------------
// Z rows: 32 half2 (128 B). Lane l owns features {2l, 2l+1}. Edge indices come
// from uniform (broadcast) csr loads; unroll-by-4 issues 4 independent row
// loads per step (MLP=4) with no shfl chain and no predication.
__global__ void __launch_bounds__(256) k_gather(const __half* __restrict__ Zh,
                                                const int* __restrict__ ptr,
                                                const int* __restrict__ csr,
                                                const float* __restrict__ inorm,
                                                const float* __restrict__ bias,
                                                float* __restrict__ Hout) {
    int v = (blockIdx.x * blockDim.x + threadIdx.x) >> 5;
    int lane = threadIdx.x & 31;
    if (v >= NN) return;
    const __half2* Z = reinterpret_cast<const __half2*>(Zh) + lane;  // row stride 32

    int beg = ptr[v], end = ptr[v + 1];

    // self loop contribution
    float2 f0 = __half22float2(Z[(long)v * 32]);
    float acc0 = f0.x, acc1 = f0.y;

    int e = beg;
    for (; e + 4 <= end; e += 4) {
        int s0 = csr[e], s1 = csr[e + 1], s2 = csr[e + 2], s3 = csr[e + 3];
        float2 a = __half22float2(Z[(long)s0 * 32]);
        float2 b = __half22float2(Z[(long)s1 * 32]);
        float2 c = __half22float2(Z[(long)s2 * 32]);
        float2 d = __half22float2(Z[(long)s3 * 32]);
        acc0 += (a.x + b.x) + (c.x + d.x);
        acc1 += (a.y + b.y) + (c.y + d.y);
    }
    for (; e < end; e++) {
        int s = csr[e];
        float2 a = __half22float2(Z[(long)s * 32]);
        acc0 += a.x;
        acc1 += a.y;
    }

    float ni = inorm[v];
    float2 bb = *reinterpret_cast<const float2*>(bias + lane * 2);
    float2 out = make_float2(ni * acc0 + bb.x, ni * acc1 + bb.y);
    *reinterpret_cast<float2*>(Hout + (long)v * 64 + lane * 2) = out;
}

__global__ void k_ids(const int* __restrict__ ids, float* out, int n) {
    int i = blockIdx.x * blockDim.x + threadIdx.x;
    if (i < n) out[NN * 64 + i] = (float)ids[i];
}

// ---------------- launch ----------------
extern "C" void kernel_launch(void* const* d_in, const int* in_sizes, int n_in,
                              void* d_out, int out_size) {
    const float* h   = (const float*)d_in[0];
    const int*   src = (const int*)d_in[1];
    const int*   dst = (const int*)d_in[2];
    const int*   ids = (const int*)d_in[3];
    const float* W0  = (const float*)d_in[4];
    const float* b0  = (const float*)d_in[5];
    const float* W1  = (const float*)d_in[6];
    const float* b1  = (const float*)d_in[7];
    const float* W2  = (const float*)d_in[8];
    const float* b2  = (const float*)d_in[9];
    float* out = (float*)d_out;
    int E = in_sizes[1];

    __half* pZ;
    float *pH, *pon, *pin;
    int *pcout, *pcin, *pptr, *pfill, *pcsr, *ppart;
    cudaGetSymbolAddress((void**)&pZ, g_Z);
    cudaGetSymbolAddress((void**)&pH, g_H);
    cudaGetSymbolAddress((void**)&pon, g_onorm);
    cudaGetSymbolAddress((void**)&pin, g_inorm);
    cudaGetSymbolAddress((void**)&pcout, g_cout);
    cudaGetSymbolAddress((void**)&pcin, g_cin);
    cudaGetSymbolAddress((void**)&pptr, g_ptr);
    cudaGetSymbolAddress((void**)&pfill, g_fill);
    cudaGetSymbolAddress((void**)&pcsr, g_csr);
    cudaGetSymbolAddress((void**)&ppart, g_part);

    cudaMemsetAsync(pcout, 0, NN * sizeof(int));
    cudaMemsetAsync(pcin, 0, NN * sizeof(int));
    k_degree<<<(E + 255) / 256, 256>>>(src, dst, pcout, pcin, E);
    k_norm<<<(NN + 255) / 256, 256>>>(pcout, pcin, pon, pin);
    k_scan_partial<<<NB_SCAN, 256>>>(pcin, ppart);
    k_scan_offsets<<<1, 1>>>(ppart, pptr);
    k_scan_write<<<NB_SCAN, 256>>>(pcin, ppart, pptr, pfill);
    k_fill<<<(E + 255) / 256, 256>>>(src, dst, pfill, pcsr, E);

    const int gblk = (NN + 127) / 128;
    const int wblk = (NN * 32 + 255) / 256;

    k_gemm<128><<<gblk, 128>>>(h, W0, pon, pZ);
    k_gather<<<wblk, 256>>>(pZ, pptr, pcsr, pin, b0, pH);
    k_gemm<64><<<gblk, 128>>>(pH, W1, pon, pZ);
    k_gather<<<wblk, 256>>>(pZ, pptr, pcsr, pin, b1, pH);
    k_gemm<64><<<gblk, 128>>>(pH, W2, pon, pZ);
    k_gather<<<wblk, 256>>>(pZ, pptr, pcsr, pin, b2, out);

    if (out_size > NN * 64) {
        int nid = out_size - NN * 64;
        if (nid > in_sizes[3]) nid = in_sizes[3];
        k_ids<<<(nid + 255) / 256, 256>>>(ids, out, nid);
    }
}

// round 5
// speedup vs baseline: 1.4115x; 1.0336x over previous
#include <cuda_runtime.h>
#include <cuda_fp16.h>

#define NN 100000
#define NE_CAP 1700000
#define NB_SCAN 98   /* ceil(100000/1024) */

// ---- scratch (device globals: allocation-free) ----
__device__ __align__(16) __half g_Z[NN * 64];   // fp16 intermediate (12.8 MB, L2-resident)
__device__ __align__(16) float  g_H[NN * 64];
__device__ float g_onorm[NN];
__device__ float g_inorm[NN];
__device__ int   g_cout[NN];
__device__ int   g_cin[NN];
__device__ int   g_ptr[NN + 1];
__device__ int   g_fill[NN];
__device__ int   g_csr[NE_CAP];
__device__ int   g_part[NB_SCAN];

// ---------------- graph preprocessing ----------------
__global__ void k_degree(const int* __restrict__ src, const int* __restrict__ dst,
                         int* cout, int* cin, int E) {
    int i = blockIdx.x * blockDim.x + threadIdx.x;
    if (i < E) {
        atomicAdd(&cout[src[i]], 1);
        atomicAdd(&cin[dst[i]], 1);
    }
}

__global__ void k_norm(const int* __restrict__ cout, const int* __restrict__ cin,
                       float* onorm, float* inorm) {
    int i = blockIdx.x * blockDim.x + threadIdx.x;
    if (i < NN) {
        onorm[i] = rsqrtf((float)(cout[i] + 1));   // +1 self loop
        inorm[i] = rsqrtf((float)(cin[i] + 1));
    }
}

__global__ void k_scan_partial(const int* __restrict__ cin, int* part) {
    __shared__ int wsum[8];
    int b = blockIdx.x, t = threadIdx.x;
    int base = b * 1024 + t * 4;
    int s = 0;
#pragma unroll
    for (int j = 0; j < 4; j++) { int i = base + j; if (i < NN) s += cin[i]; }
    for (int o = 16; o > 0; o >>= 1) s += __shfl_down_sync(0xffffffffu, s, o);
    if ((t & 31) == 0) wsum[t >> 5] = s;
    __syncthreads();
    if (t == 0) {
        int tot = 0;
        for (int w = 0; w < 8; w++) tot += wsum[w];
        part[b] = tot;
    }
}

// parallel exclusive scan of the 98 block partials (one block, 128 threads)
__global__ void k_scan_offsets(int* part, int* ptr) {
    __shared__ int wsum[4];
    int t = threadIdx.x;
    int lane = t & 31, w = t >> 5;
    int v = (t < NB_SCAN) ? part[t] : 0;
    int inc = v;
    for (int o = 1; o < 32; o <<= 1) {
        int u = __shfl_up_sync(0xffffffffu, inc, o);
        if (lane >= o) inc += u;
    }
    if (lane == 31) wsum[w] = inc;
    __syncthreads();
    if (t == 0) {
        int r = 0;
#pragma unroll
        for (int i = 0; i < 4; i++) { int x = wsum[i]; wsum[i] = r; r += x; }
    }
    __syncthreads();
    int excl = wsum[w] + inc - v;
    if (t < NB_SCAN) part[t] = excl;
    if (t == NB_SCAN - 1) ptr[NN] = excl + v;
}

__global__ void k_scan_write(const int* __restrict__ cin, const int* __restrict__ part,
                             int* ptr, int* fill) {
    __shared__ int wexc[8];
    int b = blockIdx.x, t = threadIdx.x;
    int lane = t & 31, warp = t >> 5;
    int base = b * 1024 + t * 4;
    int v[4];
#pragma unroll
    for (int j = 0; j < 4; j++) { int i = base + j; v[j] = (i < NN) ? cin[i] : 0; }
    int s = v[0] + v[1] + v[2] + v[3];
    int inc = s;
    for (int o = 1; o < 32; o <<= 1) {
        int u = __shfl_up_sync(0xffffffffu, inc, o);
        if (lane >= o) inc += u;
    }
    if (lane == 31) wexc[warp] = inc;
    __syncthreads();
    if (warp == 0) {
        int w = (lane < 8) ? wexc[lane] : 0;
        int winc = w;
        for (int o = 1; o < 8; o <<= 1) {
            int u = __shfl_up_sync(0xffffffffu, winc, o);
            if (lane >= o) winc += u;
        }
        if (lane < 8) wexc[lane] = winc - w;
    }
    __syncthreads();
    int pos = part[b] + wexc[warp] + (inc - s);
#pragma unroll
    for (int j = 0; j < 4; j++) {
        int i = base + j;
        if (i < NN) { ptr[i] = pos; fill[i] = pos; }
        pos += v[j];
    }
}

__global__ void k_fill(const int* __restrict__ src, const int* __restrict__ dst,
                       int* fill, int* csr, int E) {
    int i = blockIdx.x * blockDim.x + threadIdx.x;
    if (i < E) {
        int p = atomicAdd(&fill[dst[i]], 1);
        csr[p] = src[i];
    }
}

// scale Z rows by onorm in place (used after the race-free unscaled GEMM0)
__global__ void k_scaleZ(__half* __restrict__ Z, const float* __restrict__ onorm) {
    int v = (blockIdx.x * blockDim.x + threadIdx.x) >> 5;
    int lane = threadIdx.x & 31;
    if (v >= NN) return;
    float sc = onorm[v];
    __half2* zp = reinterpret_cast<__half2*>(Z) + (long)v * 32 + lane;
    float2 f = __half22float2(*zp);
    *zp = __floats2half2_rn(f.x * sc, f.y * sc);
}

// ---------------- dense GEMM: Z = fp16( [optional onorm .*] (A @ W) ) ----------------
template <int K, bool SCALE>
__global__ void __launch_bounds__(128, 2) k_gemm(const float* __restrict__ A,
                                                 const float* __restrict__ W,
                                                 const float* __restrict__ onorm,
                                                 __half* __restrict__ Z) {
    __shared__ float Bs[K * 64];
    const int tid = threadIdx.x;
    {
        const float4* wp = reinterpret_cast<const float4*>(W);
        float4* bs = reinterpret_cast<float4*>(Bs);
#pragma unroll
        for (int i = 0; i < (K * 16) / 128; i++)
            bs[tid + i * 128] = wp[tid + i * 128];
    }
    __syncthreads();

    const int tr = tid >> 3, tc = tid & 7;
    const int row0 = blockIdx.x * 128 + tr * 8;

    const float* ap[8];
#pragma unroll
    for (int i = 0; i < 8; i++) {
        int r = row0 + i;
        if (r > NN - 1) r = NN - 1;   // clamp: loads stay valid, stores guarded later
        ap[i] = A + (long)r * K;
    }

    float acc[8][8];
#pragma unroll
    for (int i = 0; i < 8; i++)
#pragma unroll
        for (int j = 0; j < 8; j++) acc[i][j] = 0.f;

    float4 buf0[8], buf1[8];
#pragma unroll
    for (int i = 0; i < 8; i++) buf0[i] = *reinterpret_cast<const float4*>(ap[i]);

#pragma unroll 2
    for (int k0 = 0; k0 < K; k0 += 8) {
#pragma unroll
        for (int i = 0; i < 8; i++)
            buf1[i] = *reinterpret_cast<const float4*>(ap[i] + k0 + 4);
#pragma unroll
        for (int kk = 0; kk < 4; kk++) {
            float4 w0 = *reinterpret_cast<const float4*>(&Bs[(k0 + kk) * 64 + tc * 8]);
            float4 w1 = *reinterpret_cast<const float4*>(&Bs[(k0 + kk) * 64 + tc * 8 + 4]);
            float wv[8] = {w0.x, w0.y, w0.z, w0.w, w1.x, w1.y, w1.z, w1.w};
#pragma unroll
            for (int i = 0; i < 8; i++) {
                float a = (kk == 0) ? buf0[i].x : (kk == 1) ? buf0[i].y
                        : (kk == 2) ? buf0[i].z : buf0[i].w;
#pragma unroll
                for (int j = 0; j < 8; j++) acc[i][j] += a * wv[j];
            }
        }
        if (k0 + 8 < K) {
#pragma unroll
            for (int i = 0; i < 8; i++)
                buf0[i] = *reinterpret_cast<const float4*>(ap[i] + k0 + 8);
        }
#pragma unroll
        for (int kk = 0; kk < 4; kk++) {
            float4 w0 = *reinterpret_cast<const float4*>(&Bs[(k0 + 4 + kk) * 64 + tc * 8]);
            float4 w1 = *reinterpret_cast<const float4*>(&Bs[(k0 + 4 + kk) * 64 + tc * 8 + 4]);
            float wv[8] = {w0.x, w0.y, w0.z, w0.w, w1.x, w1.y, w1.z, w1.w};
#pragma unroll
            for (int i = 0; i < 8; i++) {
                float a = (kk == 0) ? buf1[i].x : (kk == 1) ? buf1[i].y
                        : (kk == 2) ? buf1[i].z : buf1[i].w;
#pragma unroll
                for (int j = 0; j < 8; j++) acc[i][j] += a * wv[j];
            }
        }
    }

#pragma unroll
    for (int i = 0; i < 8; i++) {
        int r = row0 + i;
        if (r < NN) {
            float sc = SCALE ? onorm[r] : 1.0f;
            __half2 oo[4];
#pragma unroll
            for (int j = 0; j < 4; j++)
                oo[j] = __floats2half2_rn(acc[i][2 * j] * sc, acc[i][2 * j + 1] * sc);
            *reinterpret_cast<uint4*>(Z + (long)r * 64 + tc * 8) =
                *reinterpret_cast<uint4*>(oo);
        }
    }
}

// ---------------- SpMM gather ----------------
__global__ void __launch_bounds__(256) k_gather(const __half* __restrict__ Zh,
                                                const int* __restrict__ ptr,
                                                const int* __restrict__ csr,
                                                const float* __restrict__ inorm,
                                                const float* __restrict__ bias,
                                                float* __restrict__ Hout) {
    int v = (blockIdx.x * blockDim.x + threadIdx.x) >> 5;
    int lane = threadIdx.x & 31;
    if (v >= NN) return;
    const __half2* Z = reinterpret_cast<const __half2*>(Zh) + lane;  // row stride 32

    int beg = ptr[v], end = ptr[v + 1];
    float2 f0 = __half22float2(Z[(long)v * 32]);
    float acc0 = f0.x, acc1 = f0.y;

    int e = beg;
    for (; e + 4 <= end; e += 4) {
        int s0 = csr[e], s1 = csr[e + 1], s2 = csr[e + 2], s3 = csr[e + 3];
        float2 a = __half22float2(Z[(long)s0 * 32]);
        float2 b = __half22float2(Z[(long)s1 * 32]);
        float2 c = __half22float2(Z[(long)s2 * 32]);
        float2 d = __half22float2(Z[(long)s3 * 32]);
        acc0 += (a.x + b.x) + (c.x + d.x);
        acc1 += (a.y + b.y) + (c.y + d.y);
    }
    for (; e < end; e++) {
        int s = csr[e];
        float2 a = __half22float2(Z[(long)s * 32]);
        acc0 += a.x;
        acc1 += a.y;
    }

    float ni = inorm[v];
    float2 bb = *reinterpret_cast<const float2*>(bias + lane * 2);
    float2 out = make_float2(ni * acc0 + bb.x, ni * acc1 + bb.y);
    *reinterpret_cast<float2*>(Hout + (long)v * 64 + lane * 2) = out;
}

__global__ void k_ids(const int* __restrict__ ids, float* out, int n) {
    int i = blockIdx.x * blockDim.x + threadIdx.x;
    if (i < n) out[NN * 64 + i] = (float)ids[i];
}

// ---------------- launch ----------------
extern "C" void kernel_launch(void* const* d_in, const int* in_sizes, int n_in,
                              void* d_out, int out_size) {
    const float* h   = (const float*)d_in[0];
    const int*   src = (const int*)d_in[1];
    const int*   dst = (const int*)d_in[2];
    const int*   ids = (const int*)d_in[3];
    const float* W0  = (const float*)d_in[4];
    const float* b0  = (const float*)d_in[5];
    const float* W1  = (const float*)d_in[6];
    const float* b1  = (const float*)d_in[7];
    const float* W2  = (const float*)d_in[8];
    const float* b2  = (const float*)d_in[9];
    float* out = (float*)d_out;
    int E = in_sizes[1];

    __half* pZ;
    float *pH, *pon, *pin;
    int *pcout, *pcin, *pptr, *pfill, *pcsr, *ppart;
    cudaGetSymbolAddress((void**)&pZ, g_Z);
    cudaGetSymbolAddress((void**)&pH, g_H);
    cudaGetSymbolAddress((void**)&pon, g_onorm);
    cudaGetSymbolAddress((void**)&pin, g_inorm);
    cudaGetSymbolAddress((void**)&pcout, g_cout);
    cudaGetSymbolAddress((void**)&pcin, g_cin);
    cudaGetSymbolAddress((void**)&pptr, g_ptr);
    cudaGetSymbolAddress((void**)&pfill, g_fill);
    cudaGetSymbolAddress((void**)&pcsr, g_csr);
    cudaGetSymbolAddress((void**)&ppart, g_part);

    // lazily-created side stream + fork/join events (created on the first,
    // uncaptured correctness call; identical launch sequence every call)
    static cudaStream_t s2 = nullptr;
    static cudaEvent_t ev_fork = nullptr, ev_join = nullptr;
    if (s2 == nullptr) {
        cudaStreamCreateWithFlags(&s2, cudaStreamNonBlocking);
        cudaEventCreateWithFlags(&ev_fork, cudaEventDisableTiming);
        cudaEventCreateWithFlags(&ev_join, cudaEventDisableTiming);
    }

    const int gblk = (NN + 127) / 128;
    const int wblk = (NN * 32 + 255) / 256;

    // ---- fork: CSR/norm build on s2 concurrent with unscaled GEMM0 ----
    cudaEventRecord(ev_fork, 0);
    cudaStreamWaitEvent(s2, ev_fork, 0);

    cudaMemsetAsync(pcout, 0, NN * sizeof(int), s2);
    cudaMemsetAsync(pcin, 0, NN * sizeof(int), s2);
    k_degree<<<(E + 255) / 256, 256, 0, s2>>>(src, dst, pcout, pcin, E);
    k_norm<<<(NN + 255) / 256, 256, 0, s2>>>(pcout, pcin, pon, pin);
    k_scan_partial<<<NB_SCAN, 256, 0, s2>>>(pcin, ppart);
    k_scan_offsets<<<1, 128, 0, s2>>>(ppart, pptr);
    k_scan_write<<<NB_SCAN, 256, 0, s2>>>(pcin, ppart, pptr, pfill);
    k_fill<<<(E + 255) / 256, 256, 0, s2>>>(src, dst, pfill, pcsr, E);
    if (out_size > NN * 64) {
        int nid = out_size - NN * 64;
        if (nid > in_sizes[3]) nid = in_sizes[3];
        k_ids<<<(nid + 255) / 256, 256, 0, s2>>>(ids, out, nid);
    }
    cudaEventRecord(ev_join, s2);

    k_gemm<128, false><<<gblk, 128>>>(h, W0, pon, pZ);  // unscaled: no onorm dependence

    cudaStreamWaitEvent(0, ev_join, 0);   // join: CSR + norms ready

    k_scaleZ<<<wblk, 256>>>(pZ, pon);     // apply onorm to Z0 (~5us, L2-bound)
    k_gather<<<wblk, 256>>>(pZ, pptr, pcsr, pin, b0, pH);
    k_gemm<64, true><<<gblk, 128>>>(pH, W1, pon, pZ);
    k_gather<<<wblk, 256>>>(pZ, pptr, pcsr, pin, b1, pH);
    k_gemm<64, true><<<gblk, 128>>>(pH, W2, pon, pZ);
    k_gather<<<wblk, 256>>>(pZ, pptr, pcsr, pin, b2, out);
}

// round 6
// speedup vs baseline: 1.5475x; 1.0964x over previous
#include <cuda_runtime.h>
#include <cuda_fp16.h>

#define NN 100000
#define NE_CAP 1700000
#define NB_SCAN 98   /* ceil(100000/1024) */

// ---- scratch (device globals: allocation-free) ----
__device__ __align__(16) __half g_Ah[NN * 128];  // fp16 copy of input h (25.6 MB)
__device__ __align__(16) __half g_Hh[NN * 64];   // fp16 hidden activations
__device__ __align__(16) __half g_Z[NN * 64];    // fp16 pre-aggregation buffer
__device__ __align__(16) __half g_Wt0[64 * 128]; // W0^T fp16
__device__ __align__(16) __half g_Wt1[64 * 64];  // W1^T fp16
__device__ __align__(16) __half g_Wt2[64 * 64];  // W2^T fp16
__device__ float g_onorm[NN];
__device__ float g_inorm[NN];
__device__ int   g_cout[NN];
__device__ int   g_cin[NN];
__device__ int   g_ptr[NN + 1];
__device__ int   g_fill[NN];
__device__ int   g_csr[NE_CAP];
__device__ int   g_part[NB_SCAN];

// ---------------- graph preprocessing ----------------
__global__ void k_degree(const int* __restrict__ src, const int* __restrict__ dst,
                         int* cout, int* cin, int E) {
    int i = blockIdx.x * blockDim.x + threadIdx.x;
    if (i < E) {
        atomicAdd(&cout[src[i]], 1);
        atomicAdd(&cin[dst[i]], 1);
    }
}

__global__ void k_norm(const int* __restrict__ cout, const int* __restrict__ cin,
                       float* onorm, float* inorm) {
    int i = blockIdx.x * blockDim.x + threadIdx.x;
    if (i < NN) {
        onorm[i] = rsqrtf((float)(cout[i] + 1));   // +1 self loop
        inorm[i] = rsqrtf((float)(cin[i] + 1));
    }
}

__global__ void k_scan_partial(const int* __restrict__ cin, int* part) {
    __shared__ int wsum[8];
    int b = blockIdx.x, t = threadIdx.x;
    int base = b * 1024 + t * 4;
    int s = 0;
#pragma unroll
    for (int j = 0; j < 4; j++) { int i = base + j; if (i < NN) s += cin[i]; }
    for (int o = 16; o > 0; o >>= 1) s += __shfl_down_sync(0xffffffffu, s, o);
    if ((t & 31) == 0) wsum[t >> 5] = s;
    __syncthreads();
    if (t == 0) {
        int tot = 0;
        for (int w = 0; w < 8; w++) tot += wsum[w];
        part[b] = tot;
    }
}

// parallel exclusive scan of the 98 block partials (one block, 128 threads)
__global__ void k_scan_offsets(int* part, int* ptr) {
    __shared__ int wsum[4];
    int t = threadIdx.x;
    int lane = t & 31, w = t >> 5;
    int v = (t < NB_SCAN) ? part[t] : 0;
    int inc = v;
    for (int o = 1; o < 32; o <<= 1) {
        int u = __shfl_up_sync(0xffffffffu, inc, o);
        if (lane >= o) inc += u;
    }
    if (lane == 31) wsum[w] = inc;
    __syncthreads();
    if (t == 0) {
        int r = 0;
#pragma unroll
        for (int i = 0; i < 4; i++) { int x = wsum[i]; wsum[i] = r; r += x; }
    }
    __syncthreads();
    int excl = wsum[w] + inc - v;
    if (t < NB_SCAN) part[t] = excl;
    if (t == NB_SCAN - 1) ptr[NN] = excl + v;
}

__global__ void k_scan_write(const int* __restrict__ cin, const int* __restrict__ part,
                             int* ptr, int* fill) {
    __shared__ int wexc[8];
    int b = blockIdx.x, t = threadIdx.x;
    int lane = t & 31, warp = t >> 5;
    int base = b * 1024 + t * 4;
    int v[4];
#pragma unroll
    for (int j = 0; j < 4; j++) { int i = base + j; v[j] = (i < NN) ? cin[i] : 0; }
    int s = v[0] + v[1] + v[2] + v[3];
    int inc = s;
    for (int o = 1; o < 32; o <<= 1) {
        int u = __shfl_up_sync(0xffffffffu, inc, o);
        if (lane >= o) inc += u;
    }
    if (lane == 31) wexc[warp] = inc;
    __syncthreads();
    if (warp == 0) {
        int w = (lane < 8) ? wexc[lane] : 0;
        int winc = w;
        for (int o = 1; o < 8; o <<= 1) {
            int u = __shfl_up_sync(0xffffffffu, winc, o);
            if (lane >= o) winc += u;
        }
        if (lane < 8) wexc[lane] = winc - w;
    }
    __syncthreads();
    int pos = part[b] + wexc[warp] + (inc - s);
#pragma unroll
    for (int j = 0; j < 4; j++) {
        int i = base + j;
        if (i < NN) { ptr[i] = pos; fill[i] = pos; }
        pos += v[j];
    }
}

__global__ void k_fill(const int* __restrict__ src, const int* __restrict__ dst,
                       int* fill, int* csr, int E) {
    int i = blockIdx.x * blockDim.x + threadIdx.x;
    if (i < E) {
        int p = atomicAdd(&fill[dst[i]], 1);
        csr[p] = src[i];
    }
}

// ---------------- small converters ----------------
// h (fp32) -> Ah (fp16), 4 elems/thread
__global__ void k_h2h(const float* __restrict__ h, __half* __restrict__ Ah) {
    int idx = (blockIdx.x * blockDim.x + threadIdx.x) * 4;
    if (idx < NN * 128) {
        float4 f = *reinterpret_cast<const float4*>(h + idx);
        __half2 o[2] = {__floats2half2_rn(f.x, f.y), __floats2half2_rn(f.z, f.w)};
        *reinterpret_cast<uint2*>(Ah + idx) = *reinterpret_cast<uint2*>(o);
    }
}

// W [K,64] fp32 -> Wt [64,K] fp16 (one block)
template <int K>
__global__ void k_wt(const float* __restrict__ W, __half* __restrict__ Wt) {
    for (int i = threadIdx.x; i < 64 * K; i += blockDim.x) {
        int n = i / K, k = i % K;
        Wt[i] = __float2half(W[k * 64 + n]);
    }
}

// scale Z rows by onorm in place (after the race-free unscaled GEMM0)
__global__ void k_scaleZ(__half* __restrict__ Z, const float* __restrict__ onorm) {
    int v = (blockIdx.x * blockDim.x + threadIdx.x) >> 5;
    int lane = threadIdx.x & 31;
    if (v >= NN) return;
    float sc = onorm[v];
    __half2* zp = reinterpret_cast<__half2*>(Z) + (long)v * 32 + lane;
    float2 f = __half22float2(*zp);
    *zp = __floats2half2_rn(f.x * sc, f.y * sc);
}

// ---------------- tensor-core GEMM: Z = fp16( [onorm .*] (A @ W) ) ----------------
// A: [NN,K] fp16 row-major. Wt: [64,K] fp16 (W transposed). No smem, no syncs.
// Block = 4 warps, 64 rows; each warp does m16n8k16 MMAs over 8 n-tiles.
// k-permutation: frag position (t,h) in "low" regs (a0/a1/b0) holds physical
// k = k0+4t+h; "high" regs (a2/a3/b1) hold k = k0+4t+2+h. Applied identically
// to A and B, so the contraction is a bijective reordering of k (exact).
template <int K, bool SCALE>
__global__ void __launch_bounds__(128) k_gemm_mma(const __half* __restrict__ A,
                                                  const __half* __restrict__ Wt,
                                                  const float* __restrict__ onorm,
                                                  __half* __restrict__ Z) {
    const int tid = threadIdx.x;
    const int warp = tid >> 5, lane = tid & 31;
    const int g = lane >> 2, t = lane & 3;
    const int rbase = blockIdx.x * 64 + warp * 16;
    const int r0 = rbase + g, r1 = rbase + g + 8;
    const int r0c = r0 < NN ? r0 : NN - 1;
    const int r1c = r1 < NN ? r1 : NN - 1;
    const __half* a0p = A + (long)r0c * K + 4 * t;
    const __half* a1p = A + (long)r1c * K + 4 * t;
    const __half* wp  = Wt + (long)g * K + 4 * t;

    float acc[8][4];
#pragma unroll
    for (int n = 0; n < 8; n++)
#pragma unroll
        for (int j = 0; j < 4; j++) acc[n][j] = 0.f;

#pragma unroll
    for (int k0 = 0; k0 < K; k0 += 16) {
        uint2 aA = *reinterpret_cast<const uint2*>(a0p + k0);  // row r0: k 4t..4t+3
        uint2 aB = *reinterpret_cast<const uint2*>(a1p + k0);  // row r1
#pragma unroll
        for (int n = 0; n < 8; n++) {
            uint2 bb = *reinterpret_cast<const uint2*>(wp + (long)n * 8 * K + k0);
            asm volatile(
                "mma.sync.aligned.m16n8k16.row.col.f32.f16.f16.f32 "
                "{%0,%1,%2,%3},{%4,%5,%6,%7},{%8,%9},{%0,%1,%2,%3};"
                : "+f"(acc[n][0]), "+f"(acc[n][1]), "+f"(acc[n][2]), "+f"(acc[n][3])
                : "r"(aA.x), "r"(aB.x), "r"(aA.y), "r"(aB.y), "r"(bb.x), "r"(bb.y));
        }
    }

    float s0 = 1.f, s1 = 1.f;
    if (SCALE) { s0 = onorm[r0c]; s1 = onorm[r1c]; }
#pragma unroll
    for (int n = 0; n < 8; n++) {
        int col = n * 8 + 2 * t;
        if (r0 < NN)
            *reinterpret_cast<__half2*>(Z + (long)r0 * 64 + col) =
                __floats2half2_rn(acc[n][0] * s0, acc[n][1] * s0);
        if (r1 < NN)
            *reinterpret_cast<__half2*>(Z + (long)r1 * 64 + col) =
                __floats2half2_rn(acc[n][2] * s1, acc[n][3] * s1);
    }
}

// ---------------- SpMM gather ----------------
// Hout fp16 (hidden layers) or fp32 (final). Accumulation always fp32.
template <bool HALF_OUT>
__global__ void __launch_bounds__(256) k_gather(const __half* __restrict__ Zh,
                                                const int* __restrict__ ptr,
                                                const int* __restrict__ csr,
                                                const float* __restrict__ inorm,
                                                const float* __restrict__ bias,
                                                void* __restrict__ Hout) {
    int v = (blockIdx.x * blockDim.x + threadIdx.x) >> 5;
    int lane = threadIdx.x & 31;
    if (v >= NN) return;
    const __half2* Z = reinterpret_cast<const __half2*>(Zh) + lane;  // row stride 32

    int beg = ptr[v], end = ptr[v + 1];
    float2 f0 = __half22float2(Z[(long)v * 32]);
    float acc0 = f0.x, acc1 = f0.y;

    int e = beg;
    for (; e + 4 <= end; e += 4) {
        int s0 = csr[e], s1 = csr[e + 1], s2 = csr[e + 2], s3 = csr[e + 3];
        float2 a = __half22float2(Z[(long)s0 * 32]);
        float2 b = __half22float2(Z[(long)s1 * 32]);
        float2 c = __half22float2(Z[(long)s2 * 32]);
        float2 d = __half22float2(Z[(long)s3 * 32]);
        acc0 += (a.x + b.x) + (c.x + d.x);
        acc1 += (a.y + b.y) + (c.y + d.y);
    }
    for (; e < end; e++) {
        int s = csr[e];
        float2 a = __half22float2(Z[(long)s * 32]);
        acc0 += a.x;
        acc1 += a.y;
    }

    float ni = inorm[v];
    float2 bb = *reinterpret_cast<const float2*>(bias + lane * 2);
    float o0 = ni * acc0 + bb.x;
    float o1 = ni * acc1 + bb.y;
    if (HALF_OUT) {
        reinterpret_cast<__half2*>(Hout)[(long)v * 32 + lane] = __floats2half2_rn(o0, o1);
    } else {
        *reinterpret_cast<float2*>(reinterpret_cast<float*>(Hout) + (long)v * 64 + lane * 2) =
            make_float2(o0, o1);
    }
}

__global__ void k_ids(const int* __restrict__ ids, float* out, int n) {
    int i = blockIdx.x * blockDim.x + threadIdx.x;
    if (i < n) out[NN * 64 + i] = (float)ids[i];
}

// ---------------- launch ----------------
extern "C" void kernel_launch(void* const* d_in, const int* in_sizes, int n_in,
                              void* d_out, int out_size) {
    const float* h   = (const float*)d_in[0];
    const int*   src = (const int*)d_in[1];
    const int*   dst = (const int*)d_in[2];
    const int*   ids = (const int*)d_in[3];
    const float* W0  = (const float*)d_in[4];
    const float* b0  = (const float*)d_in[5];
    const float* W1  = (const float*)d_in[6];
    const float* b1  = (const float*)d_in[7];
    const float* W2  = (const float*)d_in[8];
    const float* b2  = (const float*)d_in[9];
    float* out = (float*)d_out;
    int E = in_sizes[1];

    __half *pAh, *pHh, *pZ, *pWt0, *pWt1, *pWt2;
    float *pon, *pin;
    int *pcout, *pcin, *pptr, *pfill, *pcsr, *ppart;
    cudaGetSymbolAddress((void**)&pAh, g_Ah);
    cudaGetSymbolAddress((void**)&pHh, g_Hh);
    cudaGetSymbolAddress((void**)&pZ, g_Z);
    cudaGetSymbolAddress((void**)&pWt0, g_Wt0);
    cudaGetSymbolAddress((void**)&pWt1, g_Wt1);
    cudaGetSymbolAddress((void**)&pWt2, g_Wt2);
    cudaGetSymbolAddress((void**)&pon, g_onorm);
    cudaGetSymbolAddress((void**)&pin, g_inorm);
    cudaGetSymbolAddress((void**)&pcout, g_cout);
    cudaGetSymbolAddress((void**)&pcin, g_cin);
    cudaGetSymbolAddress((void**)&pptr, g_ptr);
    cudaGetSymbolAddress((void**)&pfill, g_fill);
    cudaGetSymbolAddress((void**)&pcsr, g_csr);
    cudaGetSymbolAddress((void**)&ppart, g_part);

    static cudaStream_t s2 = nullptr;
    static cudaEvent_t ev_fork = nullptr, ev_join = nullptr;
    if (s2 == nullptr) {
        cudaStreamCreateWithFlags(&s2, cudaStreamNonBlocking);
        cudaEventCreateWithFlags(&ev_fork, cudaEventDisableTiming);
        cudaEventCreateWithFlags(&ev_join, cudaEventDisableTiming);
    }

    const int gblk = (NN + 63) / 64;            // MMA gemm: 64 rows/block
    const int wblk = (NN * 32 + 255) / 256;     // warp-per-node kernels

    // ---- fork: prep chain + Wt1/Wt2 on s2, concurrent with h-convert + GEMM0 ----
    cudaEventRecord(ev_fork, 0);
    cudaStreamWaitEvent(s2, ev_fork, 0);

    k_wt<64><<<1, 256, 0, s2>>>(W1, pWt1);
    k_wt<64><<<1, 256, 0, s2>>>(W2, pWt2);
    cudaMemsetAsync(pcout, 0, NN * sizeof(int), s2);
    cudaMemsetAsync(pcin, 0, NN * sizeof(int), s2);
    k_degree<<<(E + 255) / 256, 256, 0, s2>>>(src, dst, pcout, pcin, E);
    k_norm<<<(NN + 255) / 256, 256, 0, s2>>>(pcout, pcin, pon, pin);
    k_scan_partial<<<NB_SCAN, 256, 0, s2>>>(pcin, ppart);
    k_scan_offsets<<<1, 128, 0, s2>>>(ppart, pptr);
    k_scan_write<<<NB_SCAN, 256, 0, s2>>>(pcin, ppart, pptr, pfill);
    k_fill<<<(E + 255) / 256, 256, 0, s2>>>(src, dst, pfill, pcsr, E);
    if (out_size > NN * 64) {
        int nid = out_size - NN * 64;
        if (nid > in_sizes[3]) nid = in_sizes[3];
        k_ids<<<(nid + 255) / 256, 256, 0, s2>>>(ids, out, nid);
    }
    cudaEventRecord(ev_join, s2);

    // main stream: convert inputs, unscaled GEMM0 (no dependence on norms/CSR)
    k_h2h<<<(NN * 128 / 4 + 255) / 256, 256>>>(h, pAh);
    k_wt<128><<<1, 256>>>(W0, pWt0);
    k_gemm_mma<128, false><<<gblk, 128>>>(pAh, pWt0, pon, pZ);

    cudaStreamWaitEvent(0, ev_join, 0);   // join: CSR + norms ready

    k_scaleZ<<<wblk, 256>>>(pZ, pon);
    k_gather<true><<<wblk, 256>>>(pZ, pptr, pcsr, pin, b0, pHh);
    k_gemm_mma<64, true><<<gblk, 128>>>(pHh, pWt1, pon, pZ);
    k_gather<true><<<wblk, 256>>>(pZ, pptr, pcsr, pin, b1, pHh);
    k_gemm_mma<64, true><<<gblk, 128>>>(pHh, pWt2, pon, pZ);
    k_gather<false><<<wblk, 256>>>(pZ, pptr, pcsr, pin, b2, out);
}

// round 8
// speedup vs baseline: 1.7331x; 1.1199x over previous
#include <cuda_runtime.h>
#include <cuda_fp16.h>
#include <cstdint>

#define NN 100000
#define NE_CAP 1700000
#define NB_SCAN 98   /* ceil(100000/1024) */

// ---- scratch (device globals: allocation-free) ----
__device__ __align__(16) __half g_Hh[NN * 64];   // fp16 hidden activations
__device__ __align__(16) __half g_Z[NN * 64];    // fp16 pre-aggregation buffer
__device__ __align__(16) __half g_Wt0[64 * 128]; // W0^T fp16
__device__ __align__(16) __half g_Wt1[64 * 64];  // W1^T fp16
__device__ __align__(16) __half g_Wt2[64 * 64];  // W2^T fp16
__device__ float g_onorm[NN];
__device__ float g_inorm[NN];
__device__ int   g_deg[2 * NN];                  // [cout | cin], one memset
__device__ int   g_ptr[NN + 1];
__device__ int   g_fill[NN];
__device__ int   g_csr[NE_CAP];
__device__ int   g_part[NB_SCAN];

// ---------------- graph preprocessing ----------------
__global__ void k_degree(const int* __restrict__ src, const int* __restrict__ dst,
                         int* cout, int* cin, int E) {
    int i = blockIdx.x * blockDim.x + threadIdx.x;
    if (i < E) {
        atomicAdd(&cout[src[i]], 1);
        atomicAdd(&cin[dst[i]], 1);
    }
}

__global__ void k_norm(const int* __restrict__ cout, const int* __restrict__ cin,
                       float* onorm, float* inorm) {
    int i = blockIdx.x * blockDim.x + threadIdx.x;
    if (i < NN) {
        onorm[i] = rsqrtf((float)(cout[i] + 1));   // +1 self loop
        inorm[i] = rsqrtf((float)(cin[i] + 1));
    }
}

__global__ void k_scan_partial(const int* __restrict__ cin, int* part) {
    __shared__ int wsum[8];
    int b = blockIdx.x, t = threadIdx.x;
    int base = b * 1024 + t * 4;
    int s = 0;
#pragma unroll
    for (int j = 0; j < 4; j++) { int i = base + j; if (i < NN) s += cin[i]; }
    for (int o = 16; o > 0; o >>= 1) s += __shfl_down_sync(0xffffffffu, s, o);
    if ((t & 31) == 0) wsum[t >> 5] = s;
    __syncthreads();
    if (t == 0) {
        int tot = 0;
        for (int w = 0; w < 8; w++) tot += wsum[w];
        part[b] = tot;
    }
}

// parallel exclusive scan of the 98 block partials (one block, 128 threads)
__global__ void k_scan_offsets(int* part, int* ptr) {
    __shared__ int wsum[4];
    int t = threadIdx.x;
    int lane = t & 31, w = t >> 5;
    int v = (t < NB_SCAN) ? part[t] : 0;
    int inc = v;
    for (int o = 1; o < 32; o <<= 1) {
        int u = __shfl_up_sync(0xffffffffu, inc, o);
        if (lane >= o) inc += u;
    }
    if (lane == 31) wsum[w] = inc;
    __syncthreads();
    if (t == 0) {
        int r = 0;
#pragma unroll
        for (int i = 0; i < 4; i++) { int x = wsum[i]; wsum[i] = r; r += x; }
    }
    __syncthreads();
    int excl = wsum[w] + inc - v;
    if (t < NB_SCAN) part[t] = excl;
    if (t == NB_SCAN - 1) ptr[NN] = excl + v;
}

__global__ void k_scan_write(const int* __restrict__ cin, const int* __restrict__ part,
                             int* ptr, int* fill) {
    __shared__ int wexc[8];
    int b = blockIdx.x, t = threadIdx.x;
    int lane = t & 31, warp = t >> 5;
    int base = b * 1024 + t * 4;
    int v[4];
#pragma unroll
    for (int j = 0; j < 4; j++) { int i = base + j; v[j] = (i < NN) ? cin[i] : 0; }
    int s = v[0] + v[1] + v[2] + v[3];
    int inc = s;
    for (int o = 1; o < 32; o <<= 1) {
        int u = __shfl_up_sync(0xffffffffu, inc, o);
        if (lane >= o) inc += u;
    }
    if (lane == 31) wexc[warp] = inc;
    __syncthreads();
    if (warp == 0) {
        int w = (lane < 8) ? wexc[lane] : 0;
        int winc = w;
        for (int o = 1; o < 8; o <<= 1) {
            int u = __shfl_up_sync(0xffffffffu, winc, o);
            if (lane >= o) winc += u;
        }
        if (lane < 8) wexc[lane] = winc - w;
    }
    __syncthreads();
    int pos = part[b] + wexc[warp] + (inc - s);
#pragma unroll
    for (int j = 0; j < 4; j++) {
        int i = base + j;
        if (i < NN) { ptr[i] = pos; fill[i] = pos; }
        pos += v[j];
    }
}

__global__ void k_fill(const int* __restrict__ src, const int* __restrict__ dst,
                       int* fill, int* csr, int E) {
    int i = blockIdx.x * blockDim.x + threadIdx.x;
    if (i < E) {
        int p = atomicAdd(&fill[dst[i]], 1);
        csr[p] = src[i];
    }
}

// ---------------- weight transpose+convert: all three in one launch ----------------
// block 0: W0 [128,64]->Wt0 [64,128]; block 1: W1; block 2: W2
__global__ void k_wt_all(const float* __restrict__ W0, const float* __restrict__ W1,
                         const float* __restrict__ W2,
                         __half* __restrict__ Wt0, __half* __restrict__ Wt1,
                         __half* __restrict__ Wt2) {
    const float* W = (blockIdx.x == 0) ? W0 : (blockIdx.x == 1) ? W1 : W2;
    __half* Wt = (blockIdx.x == 0) ? Wt0 : (blockIdx.x == 1) ? Wt1 : Wt2;
    int K = (blockIdx.x == 0) ? 128 : 64;
    for (int i = threadIdx.x; i < 64 * K; i += blockDim.x) {
        int n = i / K, k = i % K;
        Wt[i] = __float2half(W[k * 64 + n]);
    }
}

// ---------------- tensor-core GEMM: Z = fp16( [onorm .*] (A @ W) ) ----------------
// A: [NN,K] row-major, fp32 (F32A) or fp16. Wt: [64,K] fp16. No smem, no syncs.
// Block = 4 warps, 64 rows; warp does m16n8k16 MMAs over 8 n-tiles.
// k-permutation applied identically to A and B frags -> exact contraction.
template <int K, bool SCALE, bool F32A>
__global__ void __launch_bounds__(128) k_gemm_mma(const void* __restrict__ Av,
                                                  const __half* __restrict__ Wt,
                                                  const float* __restrict__ onorm,
                                                  __half* __restrict__ Z) {
    const int tid = threadIdx.x;
    const int warp = tid >> 5, lane = tid & 31;
    const int g = lane >> 2, t = lane & 3;
    const int rbase = blockIdx.x * 64 + warp * 16;
    const int r0 = rbase + g, r1 = rbase + g + 8;
    const int r0c = r0 < NN ? r0 : NN - 1;
    const int r1c = r1 < NN ? r1 : NN - 1;
    const __half* wp = Wt + (long)g * K + 4 * t;

    float acc[8][4];
#pragma unroll
    for (int n = 0; n < 8; n++)
#pragma unroll
        for (int j = 0; j < 4; j++) acc[n][j] = 0.f;

    const float* a0f = nullptr; const float* a1f = nullptr;
    const __half* a0h = nullptr; const __half* a1h = nullptr;
    if (F32A) {
        a0f = (const float*)Av + (long)r0c * K + 4 * t;
        a1f = (const float*)Av + (long)r1c * K + 4 * t;
    } else {
        a0h = (const __half*)Av + (long)r0c * K + 4 * t;
        a1h = (const __half*)Av + (long)r1c * K + 4 * t;
    }

#pragma unroll
    for (int k0 = 0; k0 < K; k0 += 16) {
        uint2 aA, aB;
        if (F32A) {
            float4 fA = *reinterpret_cast<const float4*>(a0f + k0);
            float4 fB = *reinterpret_cast<const float4*>(a1f + k0);
            __half2 hA0 = __floats2half2_rn(fA.x, fA.y), hA1 = __floats2half2_rn(fA.z, fA.w);
            __half2 hB0 = __floats2half2_rn(fB.x, fB.y), hB1 = __floats2half2_rn(fB.z, fB.w);
            aA.x = *reinterpret_cast<unsigned int*>(&hA0);
            aA.y = *reinterpret_cast<unsigned int*>(&hA1);
            aB.x = *reinterpret_cast<unsigned int*>(&hB0);
            aB.y = *reinterpret_cast<unsigned int*>(&hB1);
        } else {
            aA = *reinterpret_cast<const uint2*>(a0h + k0);
            aB = *reinterpret_cast<const uint2*>(a1h + k0);
        }
#pragma unroll
        for (int n = 0; n < 8; n++) {
            uint2 bb = *reinterpret_cast<const uint2*>(wp + (long)n * 8 * K + k0);
            asm volatile(
                "mma.sync.aligned.m16n8k16.row.col.f32.f16.f16.f32 "
                "{%0,%1,%2,%3},{%4,%5,%6,%7},{%8,%9},{%0,%1,%2,%3};"
                : "+f"(acc[n][0]), "+f"(acc[n][1]), "+f"(acc[n][2]), "+f"(acc[n][3])
                : "r"(aA.x), "r"(aB.x), "r"(aA.y), "r"(aB.y), "r"(bb.x), "r"(bb.y));
        }
    }

    float s0 = 1.f, s1 = 1.f;
    if (SCALE) { s0 = onorm[r0c]; s1 = onorm[r1c]; }
#pragma unroll
    for (int n = 0; n < 8; n++) {
        int col = n * 8 + 2 * t;
        if (r0 < NN)
            *reinterpret_cast<__half2*>(Z + (long)r0 * 64 + col) =
                __floats2half2_rn(acc[n][0] * s0, acc[n][1] * s0);
        if (r1 < NN)
            *reinterpret_cast<__half2*>(Z + (long)r1 * 64 + col) =
                __floats2half2_rn(acc[n][2] * s1, acc[n][3] * s1);
    }
}

// ---------------- SpMM gather ----------------
// Hout fp16 (hidden layers) or fp32 (final). Accumulation always fp32.
template <bool HALF_OUT>
__global__ void __launch_bounds__(256) k_gather(const __half* __restrict__ Zh,
                                                const int* __restrict__ ptr,
                                                const int* __restrict__ csr,
                                                const float* __restrict__ inorm,
                                                const float* __restrict__ bias,
                                                void* __restrict__ Hout) {
    int v = (blockIdx.x * blockDim.x + threadIdx.x) >> 5;
    int lane = threadIdx.x & 31;
    if (v >= NN) return;
    const __half2* Z = reinterpret_cast<const __half2*>(Zh) + lane;  // row stride 32

    int beg = ptr[v], end = ptr[v + 1];
    float2 f0 = __half22float2(Z[(long)v * 32]);
    float acc0 = f0.x, acc1 = f0.y;

    int e = beg;
    for (; e + 4 <= end; e += 4) {
        int s0 = csr[e], s1 = csr[e + 1], s2 = csr[e + 2], s3 = csr[e + 3];
        float2 a = __half22float2(Z[(long)s0 * 32]);
        float2 b = __half22float2(Z[(long)s1 * 32]);
        float2 c = __half22float2(Z[(long)s2 * 32]);
        float2 d = __half22float2(Z[(long)s3 * 32]);
        acc0 += (a.x + b.x) + (c.x + d.x);
        acc1 += (a.y + b.y) + (c.y + d.y);
    }
    for (; e < end; e++) {
        int s = csr[e];
        float2 a = __half22float2(Z[(long)s * 32]);
        acc0 += a.x;
        acc1 += a.y;
    }

    float ni = inorm[v];
    float2 bb = *reinterpret_cast<const float2*>(bias + lane * 2);
    float o0 = ni * acc0 + bb.x;
    float o1 = ni * acc1 + bb.y;
    if (HALF_OUT) {
        reinterpret_cast<__half2*>(Hout)[(long)v * 32 + lane] = __floats2half2_rn(o0, o1);
    } else {
        *reinterpret_cast<float2*>(reinterpret_cast<float*>(Hout) + (long)v * 64 + lane * 2) =
            make_float2(o0, o1);
    }
}

__global__ void k_ids(const int* __restrict__ ids, float* out, int n) {
    int i = blockIdx.x * blockDim.x + threadIdx.x;
    if (i < n) out[NN * 64 + i] = (float)ids[i];
}

// ---------------- launch ----------------
extern "C" void kernel_launch(void* const* d_in, const int* in_sizes, int n_in,
                              void* d_out, int out_size) {
    const float* h   = (const float*)d_in[0];
    const int*   src = (const int*)d_in[1];
    const int*   dst = (const int*)d_in[2];
    const int*   ids = (const int*)d_in[3];
    const float* W0  = (const float*)d_in[4];
    const float* b0  = (const float*)d_in[5];
    const float* W1  = (const float*)d_in[6];
    const float* b1  = (const float*)d_in[7];
    const float* W2  = (const float*)d_in[8];
    const float* b2  = (const float*)d_in[9];
    float* out = (float*)d_out;
    int E = in_sizes[1];

    __half *pHh, *pZ, *pWt0, *pWt1, *pWt2;
    float *pon, *pin;
    int *pdeg, *pptr, *pfill, *pcsr, *ppart;
    cudaGetSymbolAddress((void**)&pHh, g_Hh);
    cudaGetSymbolAddress((void**)&pZ, g_Z);
    cudaGetSymbolAddress((void**)&pWt0, g_Wt0);
    cudaGetSymbolAddress((void**)&pWt1, g_Wt1);
    cudaGetSymbolAddress((void**)&pWt2, g_Wt2);
    cudaGetSymbolAddress((void**)&pon, g_onorm);
    cudaGetSymbolAddress((void**)&pin, g_inorm);
    cudaGetSymbolAddress((void**)&pdeg, g_deg);
    cudaGetSymbolAddress((void**)&pptr, g_ptr);
    cudaGetSymbolAddress((void**)&pfill, g_fill);
    cudaGetSymbolAddress((void**)&pcsr, g_csr);
    cudaGetSymbolAddress((void**)&ppart, g_part);
    int* pcout = pdeg;
    int* pcin  = pdeg + NN;

    static cudaStream_t s2 = nullptr;
    static cudaEvent_t ev_deg = nullptr, ev_join = nullptr;
    if (s2 == nullptr) {
        cudaStreamCreateWithFlags(&s2, cudaStreamNonBlocking);
        cudaEventCreateWithFlags(&ev_deg, cudaEventDisableTiming);
        cudaEventCreateWithFlags(&ev_join, cudaEventDisableTiming);
    }

    const int gblk = (NN + 63) / 64;            // MMA gemm: 64 rows/block
    const int wblk = (NN * 32 + 255) / 256;     // warp-per-node kernels

    // ---- main: weights, degrees, norms, then GEMM0 (fp32-A, onorm fused) ----
    k_wt_all<<<3, 256>>>(W0, W1, W2, pWt0, pWt1, pWt2);
    cudaMemsetAsync(pdeg, 0, 2 * NN * sizeof(int));
    k_degree<<<(E + 255) / 256, 256>>>(src, dst, pcout, pcin, E);
    cudaEventRecord(ev_deg, 0);
    k_norm<<<(NN + 255) / 256, 256>>>(pcout, pcin, pon, pin);
    k_gemm_mma<128, true, true><<<gblk, 128>>>(h, pWt0, pon, pZ);

    // ---- s2: CSR scan+fill chain, concurrent with norm+GEMM0 ----
    cudaStreamWaitEvent(s2, ev_deg, 0);
    k_scan_partial<<<NB_SCAN, 256, 0, s2>>>(pcin, ppart);
    k_scan_offsets<<<1, 128, 0, s2>>>(ppart, pptr);
    k_scan_write<<<NB_SCAN, 256, 0, s2>>>(pcin, ppart, pptr, pfill);
    k_fill<<<(E + 255) / 256, 256, 0, s2>>>(src, dst, pfill, pcsr, E);
    if (out_size > NN * 64) {
        int nid = out_size - NN * 64;
        if (nid > in_sizes[3]) nid = in_sizes[3];
        k_ids<<<(nid + 255) / 256, 256, 0, s2>>>(ids, out, nid);
    }
    cudaEventRecord(ev_join, s2);

    cudaStreamWaitEvent(0, ev_join, 0);   // join: CSR ready

    // ---- layer chain ----
    k_gather<true><<<wblk, 256>>>(pZ, pptr, pcsr, pin, b0, pHh);
    k_gemm_mma<64, true, false><<<gblk, 128>>>(pHh, pWt1, pon, pZ);
    k_gather<true><<<wblk, 256>>>(pZ, pptr, pcsr, pin, b1, pHh);
    k_gemm_mma<64, true, false><<<gblk, 128>>>(pHh, pWt2, pon, pZ);
    k_gather<false><<<wblk, 256>>>(pZ, pptr, pcsr, pin, b2, out);
}

// round 9
// speedup vs baseline: 1.7807x; 1.0275x over previous
#include <cuda_runtime.h>
#include <cuda_fp16.h>
#include <cstdint>

#define NN 100000
#define NE_CAP 1700000
#define NB_SCAN 98   /* ceil(100000/1024) */

// ---- scratch (device globals: allocation-free) ----
__device__ __align__(16) __half g_Hh[NN * 64];   // fp16 hidden activations
__device__ __align__(16) __half g_Z[NN * 64];    // fp16 pre-aggregation buffer
__device__ __align__(16) __half g_Wt0[64 * 128]; // W0^T fp16
__device__ __align__(16) __half g_Wt1[64 * 64];  // W1^T fp16
__device__ __align__(16) __half g_Wt2[64 * 64];  // W2^T fp16
__device__ float g_onorm[NN];
__device__ float g_inorm[NN];
__device__ int   g_deg[2 * NN];                  // [cout | cin], one memset
__device__ int   g_ptr[NN + 1];
__device__ int   g_fill[NN];
__device__ int   g_csr[NE_CAP];
__device__ int   g_part[NB_SCAN];

// ---------------- graph preprocessing ----------------
__global__ void k_degree(const int* __restrict__ src, const int* __restrict__ dst,
                         int* cout, int* cin, int E) {
    int i = blockIdx.x * blockDim.x + threadIdx.x;
    if (i < E) {
        atomicAdd(&cout[src[i]], 1);
        atomicAdd(&cin[dst[i]], 1);
    }
}

__global__ void k_norm(const int* __restrict__ cout, const int* __restrict__ cin,
                       float* onorm, float* inorm) {
    int i = blockIdx.x * blockDim.x + threadIdx.x;
    if (i < NN) {
        onorm[i] = rsqrtf((float)(cout[i] + 1));   // +1 self loop
        inorm[i] = rsqrtf((float)(cin[i] + 1));
    }
}

__global__ void k_scan_partial(const int* __restrict__ cin, int* part) {
    __shared__ int wsum[8];
    int b = blockIdx.x, t = threadIdx.x;
    int base = b * 1024 + t * 4;
    int s = 0;
#pragma unroll
    for (int j = 0; j < 4; j++) { int i = base + j; if (i < NN) s += cin[i]; }
    for (int o = 16; o > 0; o >>= 1) s += __shfl_down_sync(0xffffffffu, s, o);
    if ((t & 31) == 0) wsum[t >> 5] = s;
    __syncthreads();
    if (t == 0) {
        int tot = 0;
        for (int w = 0; w < 8; w++) tot += wsum[w];
        part[b] = tot;
    }
}

// parallel exclusive scan of the 98 block partials (one block, 128 threads)
__global__ void k_scan_offsets(int* part, int* ptr) {
    __shared__ int wsum[4];
    int t = threadIdx.x;
    int lane = t & 31, w = t >> 5;
    int v = (t < NB_SCAN) ? part[t] : 0;
    int inc = v;
    for (int o = 1; o < 32; o <<= 1) {
        int u = __shfl_up_sync(0xffffffffu, inc, o);
        if (lane >= o) inc += u;
    }
    if (lane == 31) wsum[w] = inc;
    __syncthreads();
    if (t == 0) {
        int r = 0;
#pragma unroll
        for (int i = 0; i < 4; i++) { int x = wsum[i]; wsum[i] = r; r += x; }
    }
    __syncthreads();
    int excl = wsum[w] + inc - v;
    if (t < NB_SCAN) part[t] = excl;
    if (t == NB_SCAN - 1) ptr[NN] = excl + v;
}

__global__ void k_scan_write(const int* __restrict__ cin, const int* __restrict__ part,
                             int* ptr, int* fill) {
    __shared__ int wexc[8];
    int b = blockIdx.x, t = threadIdx.x;
    int lane = t & 31, warp = t >> 5;
    int base = b * 1024 + t * 4;
    int v[4];
#pragma unroll
    for (int j = 0; j < 4; j++) { int i = base + j; v[j] = (i < NN) ? cin[i] : 0; }
    int s = v[0] + v[1] + v[2] + v[3];
    int inc = s;
    for (int o = 1; o < 32; o <<= 1) {
        int u = __shfl_up_sync(0xffffffffu, inc, o);
        if (lane >= o) inc += u;
    }
    if (lane == 31) wexc[warp] = inc;
    __syncthreads();
    if (warp == 0) {
        int w = (lane < 8) ? wexc[lane] : 0;
        int winc = w;
        for (int o = 1; o < 8; o <<= 1) {
            int u = __shfl_up_sync(0xffffffffu, winc, o);
            if (lane >= o) winc += u;
        }
        if (lane < 8) wexc[lane] = winc - w;
    }
    __syncthreads();
    int pos = part[b] + wexc[warp] + (inc - s);
#pragma unroll
    for (int j = 0; j < 4; j++) {
        int i = base + j;
        if (i < NN) { ptr[i] = pos; fill[i] = pos; }
        pos += v[j];
    }
}

__global__ void k_fill(const int* __restrict__ src, const int* __restrict__ dst,
                       int* fill, int* csr, int E) {
    int i = blockIdx.x * blockDim.x + threadIdx.x;
    if (i < E) {
        int p = atomicAdd(&fill[dst[i]], 1);
        csr[p] = src[i];
    }
}

// ---------------- weight transpose+convert: all three in one launch ----------------
__global__ void k_wt_all(const float* __restrict__ W0, const float* __restrict__ W1,
                         const float* __restrict__ W2,
                         __half* __restrict__ Wt0, __half* __restrict__ Wt1,
                         __half* __restrict__ Wt2) {
    const float* W = (blockIdx.x == 0) ? W0 : (blockIdx.x == 1) ? W1 : W2;
    __half* Wt = (blockIdx.x == 0) ? Wt0 : (blockIdx.x == 1) ? Wt1 : Wt2;
    int K = (blockIdx.x == 0) ? 128 : 64;
    for (int i = threadIdx.x; i < 64 * K; i += blockDim.x) {
        int n = i / K, k = i % K;
        Wt[i] = __float2half(W[k * 64 + n]);
    }
}

// ---------------- tensor-core GEMM: Z = fp16( [onorm .*] (A @ W) ) ----------------
// Block = 128 rows x 64 cols, 4 warps. Warp w owns cols [16w,16w+16): its B
// fragments (2 n-tiles x K/16 k-steps) are loaded ONCE into registers, then
// reused across all 8 m-tiles -> near-zero L1 B traffic (was the bottleneck:
// L1 57% in ncu). A loads are identical across warps (L1 broadcast hits).
// k-permutation applied identically to A and B frags -> exact contraction.
template <int K, bool SCALE, bool F32A>
__global__ void __launch_bounds__(128) k_gemm_mma(const void* __restrict__ Av,
                                                  const __half* __restrict__ Wt,
                                                  const float* __restrict__ onorm,
                                                  __half* __restrict__ Z) {
    const int tid = threadIdx.x;
    const int warp = tid >> 5, lane = tid & 31;
    const int g = lane >> 2, t = lane & 3;

    // B fragments in registers: Bf[k0][nn]
    uint2 Bf[K / 16][2];
#pragma unroll
    for (int k0 = 0; k0 < K / 16; k0++)
#pragma unroll
        for (int nn = 0; nn < 2; nn++)
            Bf[k0][nn] = *reinterpret_cast<const uint2*>(
                Wt + (long)(warp * 16 + nn * 8 + g) * K + k0 * 16 + 4 * t);

    const int rowblk = blockIdx.x * 128;

#pragma unroll
    for (int m = 0; m < 8; m++) {
        const int r0 = rowblk + m * 16 + g;
        const int r1 = r0 + 8;
        const int r0c = r0 < NN ? r0 : NN - 1;
        const int r1c = r1 < NN ? r1 : NN - 1;

        float acc[2][4];
#pragma unroll
        for (int nn = 0; nn < 2; nn++)
#pragma unroll
            for (int j = 0; j < 4; j++) acc[nn][j] = 0.f;

#pragma unroll
        for (int k0 = 0; k0 < K / 16; k0++) {
            uint2 aA, aB;
            if (F32A) {
                const float* a0f = (const float*)Av + (long)r0c * K + 4 * t + k0 * 16;
                const float* a1f = (const float*)Av + (long)r1c * K + 4 * t + k0 * 16;
                float4 fA = *reinterpret_cast<const float4*>(a0f);
                float4 fB = *reinterpret_cast<const float4*>(a1f);
                __half2 hA0 = __floats2half2_rn(fA.x, fA.y), hA1 = __floats2half2_rn(fA.z, fA.w);
                __half2 hB0 = __floats2half2_rn(fB.x, fB.y), hB1 = __floats2half2_rn(fB.z, fB.w);
                aA.x = *reinterpret_cast<unsigned int*>(&hA0);
                aA.y = *reinterpret_cast<unsigned int*>(&hA1);
                aB.x = *reinterpret_cast<unsigned int*>(&hB0);
                aB.y = *reinterpret_cast<unsigned int*>(&hB1);
            } else {
                const __half* a0h = (const __half*)Av + (long)r0c * K + 4 * t + k0 * 16;
                const __half* a1h = (const __half*)Av + (long)r1c * K + 4 * t + k0 * 16;
                aA = *reinterpret_cast<const uint2*>(a0h);
                aB = *reinterpret_cast<const uint2*>(a1h);
            }
#pragma unroll
            for (int nn = 0; nn < 2; nn++) {
                asm volatile(
                    "mma.sync.aligned.m16n8k16.row.col.f32.f16.f16.f32 "
                    "{%0,%1,%2,%3},{%4,%5,%6,%7},{%8,%9},{%0,%1,%2,%3};"
                    : "+f"(acc[nn][0]), "+f"(acc[nn][1]), "+f"(acc[nn][2]), "+f"(acc[nn][3])
                    : "r"(aA.x), "r"(aB.x), "r"(aA.y), "r"(aB.y),
                      "r"(Bf[k0][nn].x), "r"(Bf[k0][nn].y));
            }
        }

        float s0 = 1.f, s1 = 1.f;
        if (SCALE) { s0 = onorm[r0c]; s1 = onorm[r1c]; }
#pragma unroll
        for (int nn = 0; nn < 2; nn++) {
            int col = warp * 16 + nn * 8 + 2 * t;
            if (r0 < NN)
                *reinterpret_cast<__half2*>(Z + (long)r0 * 64 + col) =
                    __floats2half2_rn(acc[nn][0] * s0, acc[nn][1] * s0);
            if (r1 < NN)
                *reinterpret_cast<__half2*>(Z + (long)r1 * 64 + col) =
                    __floats2half2_rn(acc[nn][2] * s1, acc[nn][3] * s1);
        }
    }
}

// ---------------- SpMM gather ----------------
// acc = [onorm] . Z rows summed over in-edges + self loop; out = inorm*acc + b.
// ONORM: apply onorm[s] per source row (layer 0, where GEMM ran unscaled).
template <bool HALF_OUT, bool ONORM>
__global__ void __launch_bounds__(256) k_gather(const __half* __restrict__ Zh,
                                                const int* __restrict__ ptr,
                                                const int* __restrict__ csr,
                                                const float* __restrict__ onorm,
                                                const float* __restrict__ inorm,
                                                const float* __restrict__ bias,
                                                void* __restrict__ Hout) {
    int v = (blockIdx.x * blockDim.x + threadIdx.x) >> 5;
    int lane = threadIdx.x & 31;
    if (v >= NN) return;
    const __half2* Z = reinterpret_cast<const __half2*>(Zh) + lane;  // row stride 32

    int beg = ptr[v], end = ptr[v + 1];
    float2 f0 = __half22float2(Z[(long)v * 32]);
    float selfw = ONORM ? onorm[v] : 1.f;
    float acc0 = f0.x * selfw, acc1 = f0.y * selfw;

    int e = beg;
    for (; e + 4 <= end; e += 4) {
        int s0 = csr[e], s1 = csr[e + 1], s2 = csr[e + 2], s3 = csr[e + 3];
        float2 a = __half22float2(Z[(long)s0 * 32]);
        float2 b = __half22float2(Z[(long)s1 * 32]);
        float2 c = __half22float2(Z[(long)s2 * 32]);
        float2 d = __half22float2(Z[(long)s3 * 32]);
        if (ONORM) {
            float w0 = onorm[s0], w1 = onorm[s1], w2 = onorm[s2], w3 = onorm[s3];
            acc0 = fmaf(w0, a.x, fmaf(w1, b.x, fmaf(w2, c.x, fmaf(w3, d.x, acc0))));
            acc1 = fmaf(w0, a.y, fmaf(w1, b.y, fmaf(w2, c.y, fmaf(w3, d.y, acc1))));
        } else {
            acc0 += (a.x + b.x) + (c.x + d.x);
            acc1 += (a.y + b.y) + (c.y + d.y);
        }
    }
    for (; e < end; e++) {
        int s = csr[e];
        float2 a = __half22float2(Z[(long)s * 32]);
        float w = ONORM ? onorm[s] : 1.f;
        acc0 = fmaf(w, a.x, acc0);
        acc1 = fmaf(w, a.y, acc1);
    }

    float ni = inorm[v];
    float2 bb = *reinterpret_cast<const float2*>(bias + lane * 2);
    float o0 = ni * acc0 + bb.x;
    float o1 = ni * acc1 + bb.y;
    if (HALF_OUT) {
        reinterpret_cast<__half2*>(Hout)[(long)v * 32 + lane] = __floats2half2_rn(o0, o1);
    } else {
        *reinterpret_cast<float2*>(reinterpret_cast<float*>(Hout) + (long)v * 64 + lane * 2) =
            make_float2(o0, o1);
    }
}

__global__ void k_ids(const int* __restrict__ ids, float* out, int n) {
    int i = blockIdx.x * blockDim.x + threadIdx.x;
    if (i < n) out[NN * 64 + i] = (float)ids[i];
}

// ---------------- launch ----------------
extern "C" void kernel_launch(void* const* d_in, const int* in_sizes, int n_in,
                              void* d_out, int out_size) {
    const float* h   = (const float*)d_in[0];
    const int*   src = (const int*)d_in[1];
    const int*   dst = (const int*)d_in[2];
    const int*   ids = (const int*)d_in[3];
    const float* W0  = (const float*)d_in[4];
    const float* b0  = (const float*)d_in[5];
    const float* W1  = (const float*)d_in[6];
    const float* b1  = (const float*)d_in[7];
    const float* W2  = (const float*)d_in[8];
    const float* b2  = (const float*)d_in[9];
    float* out = (float*)d_out;
    int E = in_sizes[1];

    __half *pHh, *pZ, *pWt0, *pWt1, *pWt2;
    float *pon, *pin;
    int *pdeg, *pptr, *pfill, *pcsr, *ppart;
    cudaGetSymbolAddress((void**)&pHh, g_Hh);
    cudaGetSymbolAddress((void**)&pZ, g_Z);
    cudaGetSymbolAddress((void**)&pWt0, g_Wt0);
    cudaGetSymbolAddress((void**)&pWt1, g_Wt1);
    cudaGetSymbolAddress((void**)&pWt2, g_Wt2);
    cudaGetSymbolAddress((void**)&pon, g_onorm);
    cudaGetSymbolAddress((void**)&pin, g_inorm);
    cudaGetSymbolAddress((void**)&pdeg, g_deg);
    cudaGetSymbolAddress((void**)&pptr, g_ptr);
    cudaGetSymbolAddress((void**)&pfill, g_fill);
    cudaGetSymbolAddress((void**)&pcsr, g_csr);
    cudaGetSymbolAddress((void**)&ppart, g_part);
    int* pcout = pdeg;
    int* pcin  = pdeg + NN;

    static cudaStream_t s2 = nullptr;
    static cudaEvent_t ev_fork = nullptr, ev_join = nullptr;
    if (s2 == nullptr) {
        cudaStreamCreateWithFlags(&s2, cudaStreamNonBlocking);
        cudaEventCreateWithFlags(&ev_fork, cudaEventDisableTiming);
        cudaEventCreateWithFlags(&ev_join, cudaEventDisableTiming);
    }

    const int gblk = (NN + 127) / 128;          // MMA gemm: 128 rows/block
    const int wblk = (NN * 32 + 255) / 256;     // warp-per-node kernels

    // ---- fork: whole prep chain on s2, GEMM0 (unscaled) on main ----
    cudaEventRecord(ev_fork, 0);
    cudaStreamWaitEvent(s2, ev_fork, 0);

    cudaMemsetAsync(pdeg, 0, 2 * NN * sizeof(int), s2);
    k_degree<<<(E + 255) / 256, 256, 0, s2>>>(src, dst, pcout, pcin, E);
    k_norm<<<(NN + 255) / 256, 256, 0, s2>>>(pcout, pcin, pon, pin);
    k_scan_partial<<<NB_SCAN, 256, 0, s2>>>(pcin, ppart);
    k_scan_offsets<<<1, 128, 0, s2>>>(ppart, pptr);
    k_scan_write<<<NB_SCAN, 256, 0, s2>>>(pcin, ppart, pptr, pfill);
    k_fill<<<(E + 255) / 256, 256, 0, s2>>>(src, dst, pfill, pcsr, E);
    if (out_size > NN * 64) {
        int nid = out_size - NN * 64;
        if (nid > in_sizes[3]) nid = in_sizes[3];
        k_ids<<<(nid + 255) / 256, 256, 0, s2>>>(ids, out, nid);
    }
    cudaEventRecord(ev_join, s2);

    k_wt_all<<<3, 256>>>(W0, W1, W2, pWt0, pWt1, pWt2);
    k_gemm_mma<128, false, true><<<gblk, 128>>>(h, pWt0, pon, pZ);

    cudaStreamWaitEvent(0, ev_join, 0);   // join: CSR + norms ready

    // ---- layer chain (gather0 applies onorm per source row) ----
    k_gather<true, true><<<wblk, 256>>>(pZ, pptr, pcsr, pon, pin, b0, pHh);
    k_gemm_mma<64, true, false><<<gblk, 128>>>(pHh, pWt1, pon, pZ);
    k_gather<true, false><<<wblk, 256>>>(pZ, pptr, pcsr, pon, pin, b1, pHh);
    k_gemm_mma<64, true, false><<<gblk, 128>>>(pHh, pWt2, pon, pZ);
    k_gather<false, false><<<wblk, 256>>>(pZ, pptr, pcsr, pon, pin, b2, out);
}